// round 5
// baseline (speedup 1.0000x reference)
#include <cuda_runtime.h>
#include <cstdint>

// TaylorExp: out row (273) = [1, x*0.5 (16), outer(sx,sx) (256)]
// sx = x * sqrt(1/(sqrt(2)*sqrt(16)))
//
// Round-5: 32 rows per block (each of 8 warps computes 4 rows into smem),
// flushed by ONE 34,944-byte TMA bulk store with L2::evict_first policy.
// Bigger TMA chunks -> longer sequential DRAM bursts, 4x fewer fence/commit ops.

#define QUAD_SQRT_SCALE 0.42044820762685725f
#define T1_SCALE        0.5f
#define ROWS_PER_WARP   4
#define ROWS_PER_BLOCK  32                            // 8 warps * 4 rows
#define ROW_LEN         273
#define BLOCK_FLOATS    (ROWS_PER_BLOCK * ROW_LEN)    // 8736
#define BLOCK_BYTES     (BLOCK_FLOATS * 4)            // 34944, multiple of 16

__global__ void __launch_bounds__(256) taylor_exp_kernel(
    const float* __restrict__ x,
    float* __restrict__ out,
    int rows)
{
    __shared__ __align__(16) float s[BLOCK_FLOATS];

    const int warp = threadIdx.x >> 5;
    const int lane = threadIdx.x & 31;
    const int row0 = blockIdx.x * ROWS_PER_BLOCK + warp * ROWS_PER_WARP;

    #pragma unroll
    for (int r = 0; r < ROWS_PER_WARP; r++) {
        const int row = row0 + r;
        if (row >= rows) break;

        float* __restrict__ srow = s + (warp * ROWS_PER_WARP + r) * ROW_LEN;
        float xv = (lane < 16) ? x[(size_t)row * 16 + lane] : 0.0f;

        if (lane < 16)  srow[1 + lane] = xv * T1_SCALE;
        if (lane == 16) srow[0] = 1.0f;

        float sx = xv * QUAD_SQRT_SCALE;
        #pragma unroll
        for (int k = 0; k < 8; k++) {
            int q = lane + 32 * k;                       // 0..255
            float vr = __shfl_sync(0xffffffffu, sx, q >> 4);
            float vc = __shfl_sync(0xffffffffu, sx, q & 15);
            srow[17 + q] = vr * vc;
        }
    }
    __syncthreads();

    const size_t base = (size_t)blockIdx.x * BLOCK_FLOATS;
    const int valid_rows = min(ROWS_PER_BLOCK, rows - blockIdx.x * ROWS_PER_BLOCK);

    if (valid_rows == ROWS_PER_BLOCK) {
        if (threadIdx.x == 0) {
            uint32_t saddr = (uint32_t)__cvta_generic_to_shared(s);
            float* gdst = out + base;
            asm volatile("fence.proxy.async.shared::cta;" ::: "memory");
            asm volatile(
                "{\n\t"
                ".reg .b64 pol;\n\t"
                "createpolicy.fractional.L2::evict_first.b64 pol, 1.0;\n\t"
                "cp.async.bulk.global.shared::cta.bulk_group.L2::cache_hint"
                " [%0], [%1], %2, pol;\n\t"
                "}"
                :: "l"(gdst), "r"(saddr), "r"((uint32_t)BLOCK_BYTES)
                : "memory");
            asm volatile("cp.async.bulk.commit_group;" ::: "memory");
            asm volatile("cp.async.bulk.wait_group 0;" ::: "memory");
        }
    } else if (valid_rows > 0) {
        // tail block: scalar bounds-checked flush (not hit for bench shape)
        const int nfloats = valid_rows * ROW_LEN;
        for (int i = threadIdx.x; i < nfloats; i += 256)
            out[base + i] = s[i];
    }
}

extern "C" void kernel_launch(void* const* d_in, const int* in_sizes, int n_in,
                              void* d_out, int out_size)
{
    const float* x = (const float*)d_in[0];
    float* out = (float*)d_out;

    int rows = in_sizes[0] / 16;
    int blocks = (rows + ROWS_PER_BLOCK - 1) / ROWS_PER_BLOCK;

    taylor_exp_kernel<<<blocks, 256>>>(x, out, rows);
}

// round 6
// speedup vs baseline: 1.0042x; 1.0042x over previous
#include <cuda_runtime.h>
#include <cstdint>

// TaylorExp: out row (273) = [1, x*0.5 (16), outer(sx,sx) (256)]
// sx = x * sqrt(1/(sqrt(2)*sqrt(16)))
//
// Round-6: fully warp-independent pipeline. Each warp computes 4 rows into its
// private smem chunk (4368 B, 16B-multiple & 16B-aligned in gmem), then issues
// its OWN evict-first TMA bulk store and waits its own group. No __syncthreads,
// no cross-warp coupling -> 2x more outstanding bulk stores than R4 and
// compute/store overlap across warps.

#define QUAD_SQRT_SCALE 0.42044820762685725f
#define T1_SCALE        0.5f
#define ROWS_PER_WARP   4
#define WARPS_PER_BLOCK 8
#define ROWS_PER_BLOCK  (ROWS_PER_WARP * WARPS_PER_BLOCK)  // 32
#define ROW_LEN         273
#define WARP_FLOATS     (ROWS_PER_WARP * ROW_LEN)          // 1092
#define WARP_BYTES      (WARP_FLOATS * 4)                  // 4368 = 273*16
#define BLOCK_FLOATS    (ROWS_PER_BLOCK * ROW_LEN)

__global__ void __launch_bounds__(256) taylor_exp_kernel(
    const float* __restrict__ x,
    float* __restrict__ out,
    int rows)
{
    __shared__ __align__(16) float s[BLOCK_FLOATS];

    const int warp = threadIdx.x >> 5;
    const int lane = threadIdx.x & 31;
    const int row0 = blockIdx.x * ROWS_PER_BLOCK + warp * ROWS_PER_WARP;

    float* __restrict__ swarp = s + warp * WARP_FLOATS;

    const bool full = (row0 + ROWS_PER_WARP) <= rows;

    #pragma unroll
    for (int r = 0; r < ROWS_PER_WARP; r++) {
        const int row = row0 + r;
        if (row >= rows) break;

        float* __restrict__ srow = swarp + r * ROW_LEN;
        float xv = (lane < 16) ? x[(size_t)row * 16 + lane] : 0.0f;

        if (lane < 16)  srow[1 + lane] = xv * T1_SCALE;
        if (lane == 16) srow[0] = 1.0f;

        float sx = xv * QUAD_SQRT_SCALE;
        #pragma unroll
        for (int k = 0; k < 8; k++) {
            int q = lane + 32 * k;                       // 0..255
            float vr = __shfl_sync(0xffffffffu, sx, q >> 4);
            float vc = __shfl_sync(0xffffffffu, sx, q & 15);
            srow[17 + q] = vr * vc;
        }
    }

    __syncwarp();

    if (full) {
        // per-warp bulk store of this warp's 4 rows; only lane 0 issues+waits.
        if (lane == 0) {
            uint32_t saddr = (uint32_t)__cvta_generic_to_shared(swarp);
            float* gdst = out + (size_t)row0 * ROW_LEN;
            asm volatile("fence.proxy.async.shared::cta;" ::: "memory");
            asm volatile(
                "{\n\t"
                ".reg .b64 pol;\n\t"
                "createpolicy.fractional.L2::evict_first.b64 pol, 1.0;\n\t"
                "cp.async.bulk.global.shared::cta.bulk_group.L2::cache_hint"
                " [%0], [%1], %2, pol;\n\t"
                "}"
                :: "l"(gdst), "r"(saddr), "r"((uint32_t)WARP_BYTES)
                : "memory");
            asm volatile("cp.async.bulk.commit_group;" ::: "memory");
            asm volatile("cp.async.bulk.wait_group 0;" ::: "memory");
        }
    } else if (row0 < rows) {
        // tail warp: scalar bounds-checked flush (not hit for bench shape)
        const int nfloats = (rows - row0) * ROW_LEN;
        for (int i = lane; i < nfloats; i += 32)
            out[(size_t)row0 * ROW_LEN + i] = swarp[i];
    }
}

extern "C" void kernel_launch(void* const* d_in, const int* in_sizes, int n_in,
                              void* d_out, int out_size)
{
    const float* x = (const float*)d_in[0];
    float* out = (float*)d_out;

    int rows = in_sizes[0] / 16;
    int blocks = (rows + ROWS_PER_BLOCK - 1) / ROWS_PER_BLOCK;

    taylor_exp_kernel<<<blocks, 256>>>(x, out, rows);
}

// round 7
// speedup vs baseline: 1.0533x; 1.0488x over previous
#include <cuda_runtime.h>
#include <cstdint>

// TaylorExp: out row (273) = [1, x*0.5 (16), outer(sx,sx) (256)]
// sx = x * sqrt(1/(sqrt(2)*sqrt(16)))
//
// Round-7: maximize CTA concurrency. 128-thread blocks (4 warps), 4 rows/block,
// one 4368-byte evict-first TMA bulk store per block. smem 4.4KB -> ~16 CTAs/SM,
// ~2.5x more independent write streams in flight than R4.

#define QUAD_SQRT_SCALE 0.42044820762685725f
#define T1_SCALE        0.5f
#define ROWS_PER_BLOCK  4
#define THREADS         128
#define ROW_LEN         273
#define BLOCK_FLOATS    (ROWS_PER_BLOCK * ROW_LEN)   // 1092
#define BLOCK_BYTES     (BLOCK_FLOATS * 4)           // 4368 = 273*16

__global__ void __launch_bounds__(THREADS) taylor_exp_kernel(
    const float* __restrict__ x,
    float* __restrict__ out,
    int rows)
{
    __shared__ __align__(16) float s[BLOCK_FLOATS];

    const int warp = threadIdx.x >> 5;
    const int lane = threadIdx.x & 31;
    const int row  = blockIdx.x * ROWS_PER_BLOCK + warp;

    if (row < rows) {
        float* __restrict__ srow = s + warp * ROW_LEN;
        float xv = (lane < 16) ? x[(size_t)row * 16 + lane] : 0.0f;

        if (lane < 16)  srow[1 + lane] = xv * T1_SCALE;
        if (lane == 16) srow[0] = 1.0f;

        float sx = xv * QUAD_SQRT_SCALE;
        #pragma unroll
        for (int k = 0; k < 8; k++) {
            int q = lane + 32 * k;                       // 0..255
            float vr = __shfl_sync(0xffffffffu, sx, q >> 4);
            float vc = __shfl_sync(0xffffffffu, sx, q & 15);
            srow[17 + q] = vr * vc;
        }
    }
    __syncthreads();

    const size_t base = (size_t)blockIdx.x * BLOCK_FLOATS;
    const int valid_rows = min(ROWS_PER_BLOCK, rows - blockIdx.x * ROWS_PER_BLOCK);

    if (valid_rows == ROWS_PER_BLOCK) {
        if (threadIdx.x == 0) {
            uint32_t saddr = (uint32_t)__cvta_generic_to_shared(s);
            float* gdst = out + base;
            asm volatile("fence.proxy.async.shared::cta;" ::: "memory");
            asm volatile(
                "{\n\t"
                ".reg .b64 pol;\n\t"
                "createpolicy.fractional.L2::evict_first.b64 pol, 1.0;\n\t"
                "cp.async.bulk.global.shared::cta.bulk_group.L2::cache_hint"
                " [%0], [%1], %2, pol;\n\t"
                "}"
                :: "l"(gdst), "r"(saddr), "r"((uint32_t)BLOCK_BYTES)
                : "memory");
            asm volatile("cp.async.bulk.commit_group;" ::: "memory");
            asm volatile("cp.async.bulk.wait_group 0;" ::: "memory");
        }
    } else if (valid_rows > 0) {
        // tail block: scalar bounds-checked flush (not hit for bench shape)
        const int nfloats = valid_rows * ROW_LEN;
        for (int i = threadIdx.x; i < nfloats; i += THREADS)
            out[base + i] = s[i];
    }
}

extern "C" void kernel_launch(void* const* d_in, const int* in_sizes, int n_in,
                              void* d_out, int out_size)
{
    const float* x = (const float*)d_in[0];
    float* out = (float*)d_out;

    int rows = in_sizes[0] / 16;
    int blocks = (rows + ROWS_PER_BLOCK - 1) / ROWS_PER_BLOCK;

    taylor_exp_kernel<<<blocks, THREADS>>>(x, out, rows);
}